// round 13
// baseline (speedup 1.0000x reference)
#include <cuda_runtime.h>
#include <cuda_bf16.h>
#include <cstdint>
#include <float.h>

#define DINL __device__ __forceinline__

// ---------------- scratch (__device__ globals; no allocs allowed) ----------------
__device__ __nv_bfloat16 g_B[128 * 512];        // W^T bf16, [e][k] k-contiguous
__device__ float g_WT[128 * 512];               // W^T fp32, [e][k] (for exact recompute)
__device__ float g_cand[1024 * 128 * 10];       // per-(128-row chunk,e): 5 max + 5 min
__device__ int   g_candIdx[1024 * 128 * 10];    // row-in-batch indices for the above
__device__ float g_pooled[32 * 128];

// ---------------- helpers ----------------
DINL uint32_t smem_u32(const void* p) {
    uint32_t a;
    asm("{ .reg .u64 t; cvta.to.shared.u64 t, %1; cvt.u32.u64 %0, t; }" : "=r"(a) : "l"(p));
    return a;
}

DINL void ldmatrix4(uint32_t& r0, uint32_t& r1, uint32_t& r2, uint32_t& r3, uint32_t addr) {
    asm volatile("ldmatrix.sync.aligned.m8n8.x4.shared.b16 {%0,%1,%2,%3}, [%4];"
                 : "=r"(r0), "=r"(r1), "=r"(r2), "=r"(r3) : "r"(addr));
}

DINL void mma16816(float* c, uint32_t a0, uint32_t a1, uint32_t a2, uint32_t a3,
                   uint32_t b0, uint32_t b1) {
    asm volatile(
        "mma.sync.aligned.m16n8k16.row.col.f32.bf16.bf16.f32 "
        "{%0,%1,%2,%3}, {%4,%5,%6,%7}, {%8,%9}, {%0,%1,%2,%3};"
        : "+f"(c[0]), "+f"(c[1]), "+f"(c[2]), "+f"(c[3])
        : "r"(a0), "r"(a1), "r"(a2), "r"(a3), "r"(b0), "r"(b1));
}

DINL void cp_async16(uint32_t dst, const void* src) {
    asm volatile("cp.async.cg.shared.global [%0], [%1], 16;" :: "r"(dst), "l"(src) : "memory");
}
DINL void cp_commit() { asm volatile("cp.async.commit_group;" ::: "memory"); }
DINL void cp_wait0()  { asm volatile("cp.async.wait_group 0;" ::: "memory"); }

DINL uint32_t packbf(float x, float y) {
    __nv_bfloat162 p = __floats2bfloat162_rn(x, y);
    return *(uint32_t*)&p;
}

// sorted-5 insertion, max side (v0>=..>=v4)
DINL void ins5max(float v, int i, float& v0, int& i0, float& v1, int& i1,
                  float& v2, int& i2, float& v3, int& i3, float& v4, int& i4) {
    if (v > v4) {
        if (v > v2) {
            if (v > v0)      { v4=v3;i4=i3; v3=v2;i3=i2; v2=v1;i2=i1; v1=v0;i1=i0; v0=v;i0=i; }
            else if (v > v1) { v4=v3;i4=i3; v3=v2;i3=i2; v2=v1;i2=i1; v1=v;i1=i; }
            else             { v4=v3;i4=i3; v3=v2;i3=i2; v2=v;i2=i; }
        } else {
            if (v > v3)      { v4=v3;i4=i3; v3=v;i3=i; }
            else             { v4=v;i4=i; }
        }
    }
}
// sorted-5 insertion, min side (v0<=..<=v4)
DINL void ins5min(float v, int i, float& v0, int& i0, float& v1, int& i1,
                  float& v2, int& i2, float& v3, int& i3, float& v4, int& i4) {
    if (v < v4) {
        if (v < v2) {
            if (v < v0)      { v4=v3;i4=i3; v3=v2;i3=i2; v2=v1;i2=i1; v1=v0;i1=i0; v0=v;i0=i; }
            else if (v < v1) { v4=v3;i4=i3; v3=v2;i3=i2; v2=v1;i2=i1; v1=v;i1=i; }
            else             { v4=v3;i4=i3; v3=v2;i3=i2; v2=v;i2=i; }
        } else {
            if (v < v3)      { v4=v3;i4=i3; v3=v;i3=i; }
            else             { v4=v;i4=i; }
        }
    }
}

// ---------------- kernel 1: W [512,128] fp32 -> g_B bf16 + g_WT fp32 ([e][k]) ----------------
__global__ void prep_B_kernel(const float* __restrict__ W) {
    int idx = blockIdx.x * 256 + threadIdx.x;   // 65536
    int k = idx >> 7, e = idx & 127;
    float v = W[idx];
    g_B[e * 512 + k] = __float2bfloat16(v);
    g_WT[e * 512 + k] = v;
}

// ---------------- kernel 2: zero-sync direct-LDG bf16 HMMA GEMM + top5/bot5 ----------------
// CTA: 256 rows x 128 e, 512 threads = 16 warps; warp w owns rows w*16..w*16+15 (full 128 e).
// A fragments loaded DIRECTLY from global (no smem, no staging, no sync in K-loop).
// B (128KB bf16, (c16 ^ (e&7)) swizzle) resident in smem, read via ldmatrix.
static constexpr int B_BYTES = 131072;
static constexpr int SM_BYTES = B_BYTES;            // epilogue fb (67584) reuses this region

__global__ void __launch_bounds__(512, 1) gemm_pool_kernel(const float* __restrict__ x) {
    extern __shared__ __align__(128) char smem[];
    const uint32_t sb = smem_u32(smem);
    const int tid = threadIdx.x, lane = tid & 31, wid = tid >> 5;   // wid 0..15
    const int cta = blockIdx.x;
    const float* xg = x + (size_t)cta * 256 * 512;
    const int wrow = wid * 16;                       // warp's first row (0..240)

    // ---- B resident: 8192 x 16B cp.async, swizzled (c16 ^ (e&7)) within 1KB rows ----
    #pragma unroll
    for (int i = 0; i < 16; i++) {
        int u = tid + 512 * i;
        int e = u >> 6, c = u & 63;
        uint32_t dst = sb + (uint32_t)(e * 1024 + ((c ^ (e & 7)) << 4));
        cp_async16(dst, (const char*)g_B + (size_t)u * 16);
    }
    cp_commit();
    cp_wait0();
    __syncthreads();     // publish B — the ONLY sync before the epilogue

    // ---- accumulators: warp tile 16(m) x 128(n) = 64 regs ----
    float acc[16][4];
    #pragma unroll
    for (int i = 0; i < 16; i++)
        #pragma unroll
        for (int j = 0; j < 4; j++) acc[i][j] = 0.f;

    // A fragment global base: row wrow + (lane>>2), k byte-pairs at 2*(lane&3)
    const float* arow0 = xg + (size_t)(wrow + (lane >> 2)) * 512 + 2 * (lane & 3);
    // B ldmatrix per-lane bases (constant across K): one per 16-e block
    uint32_t bbase[8];
    #pragma unroll
    for (int nb = 0; nb < 8; nb++)
        bbase[nb] = sb + (uint32_t)(nb * 16384 + (lane & 15) * 1024);
    const uint32_t lxor = (uint32_t)(lane & 7);
    const uint32_t lhalf = (uint32_t)(lane >> 4);

    // ---- K loop: 32 k16-steps, zero synchronization, deep-MLP global A streaming ----
    #pragma unroll 4
    for (int step = 0; step < 32; step++) {
        const float* ap = arow0 + step * 16;
        float2 p00 = __ldg((const float2*)(ap));
        float2 p10 = __ldg((const float2*)(ap + 8 * 512));
        float2 p01 = __ldg((const float2*)(ap + 8));
        float2 p11 = __ldg((const float2*)(ap + 8 * 512 + 8));
        uint32_t a0 = packbf(p00.x, p00.y), a1 = packbf(p10.x, p10.y);
        uint32_t a2 = packbf(p01.x, p01.y), a3 = packbf(p11.x, p11.y);

        const uint32_t c16 = (uint32_t)(step * 2) + lhalf;
        const uint32_t sw = ((c16 ^ lxor) << 4);
        #pragma unroll
        for (int nb = 0; nb < 8; nb++) {
            uint32_t b0, b1, b2, b3;
            ldmatrix4(b0, b1, b2, b3, bbase[nb] + sw);
            mma16816(acc[nb * 2], a0, a1, a2, a3, b0, b2);
            mma16816(acc[nb * 2 + 1], a0, a1, a2, a3, b1, b3);
        }
    }

    __syncthreads();   // all B reads done; smem reusable as fb

    // ---- epilogue: two 128-row halves through fb[128][132] (reused B region) ----
    float* fb = (float*)smem;
    for (int half = 0; half < 2; half++) {
        if ((wid >> 3) == half) {
            int r0 = (wid & 7) * 16 + (lane >> 2);
            #pragma unroll
            for (int nb = 0; nb < 8; nb++)
                #pragma unroll
                for (int h = 0; h < 2; h++) {
                    int c = nb * 16 + h * 8 + (lane & 3) * 2;
                    float* a4 = acc[nb * 2 + h];
                    fb[r0 * 132 + c] = a4[0];
                    fb[r0 * 132 + c + 1] = a4[1];
                    fb[(r0 + 8) * 132 + c] = a4[2];
                    fb[(r0 + 8) * 132 + c + 1] = a4[3];
                }
        }
        __syncthreads();
        if (tid < 128) {
            const int e = tid;
            const int chunkIdx = cta * 2 + half;        // 128-row chunk id (0..1023)
            float t0=-FLT_MAX,t1=-FLT_MAX,t2=-FLT_MAX,t3=-FLT_MAX,t4=-FLT_MAX;
            int   a0i=0,a1i=0,a2i=0,a3i=0,a4i=0;
            float u0=FLT_MAX,u1=FLT_MAX,u2=FLT_MAX,u3=FLT_MAX,u4=FLT_MAX;
            int   b0i=0,b1i=0,b2i=0,b3i=0,b4i=0;
            const int rbase = (chunkIdx & 31) * 128;    // row-in-batch offset
            for (int r = 0; r < 128; r++) {
                float v = fb[r * 132 + e];
                ins5max(v, rbase + r, t0,a0i, t1,a1i, t2,a2i, t3,a3i, t4,a4i);
                ins5min(v, rbase + r, u0,b0i, u1,b1i, u2,b2i, u3,b3i, u4,b4i);
            }
            size_t o = ((size_t)chunkIdx * 128 + e) * 10;
            g_cand[o+0]=t0; g_cand[o+1]=t1; g_cand[o+2]=t2; g_cand[o+3]=t3; g_cand[o+4]=t4;
            g_cand[o+5]=u0; g_cand[o+6]=u1; g_cand[o+7]=u2; g_cand[o+8]=u3; g_cand[o+9]=u4;
            g_candIdx[o+0]=a0i; g_candIdx[o+1]=a1i; g_candIdx[o+2]=a2i; g_candIdx[o+3]=a3i; g_candIdx[o+4]=a4i;
            g_candIdx[o+5]=b0i; g_candIdx[o+6]=b1i; g_candIdx[o+7]=b2i; g_candIdx[o+8]=b3i; g_candIdx[o+9]=b4i;
        }
        __syncthreads();
    }
}

// ---------------- kernel 3: merge chunks, exact fp32 recompute, pool ----------------
// grid = 4096 (b*128+e), block = 64 (warp0: max side, warp1: min side)
__global__ void merge_pool_kernel(const float* __restrict__ x) {
    const int blk = blockIdx.x;
    const int b = blk >> 7, e = blk & 127;
    const int tid = threadIdx.x, lane = tid & 31, w = tid >> 5;
    __shared__ int s_idx[10];
    __shared__ float s_exact[10];
    __shared__ float s_wcol[512];

    {
        const float4* wt = (const float4*)(g_WT + (size_t)e * 512);
        ((float4*)s_wcol)[tid] = wt[tid];
        ((float4*)s_wcol)[tid + 64] = wt[tid + 64];
    }

    // phase 1: each lane owns one of 32 chunks; warp-merge sorted-5 lists -> global top5
    {
        size_t base = (((size_t)(b * 32 + lane)) * 128 + e) * 10 + (w ? 5 : 0);
        float v0, v1, v2, v3, v4;
        int j0, j1, j2, j3, j4;
        v0 = g_cand[base+0]; v1 = g_cand[base+1]; v2 = g_cand[base+2];
        v3 = g_cand[base+3]; v4 = g_cand[base+4];
        j0 = g_candIdx[base+0]; j1 = g_candIdx[base+1]; j2 = g_candIdx[base+2];
        j3 = g_candIdx[base+3]; j4 = g_candIdx[base+4];
        if (w) { v0 = -v0; v1 = -v1; v2 = -v2; v3 = -v3; v4 = -v4; }

        #pragma unroll
        for (int r = 0; r < 5; r++) {
            float cur = v0;
            float m = cur;
            #pragma unroll
            for (int s = 16; s; s >>= 1) m = fmaxf(m, __shfl_xor_sync(0xffffffffu, m, s));
            unsigned ball = __ballot_sync(0xffffffffu, cur == m);
            int win = __ffs(ball) - 1;
            int widx = __shfl_sync(0xffffffffu, j0, win);
            if (lane == 0) s_idx[w * 5 + r] = widx;
            if (lane == win) { v0=v1; j0=j1; v1=v2; j1=j2; v2=v3; j2=j3; v3=v4; j3=j4; v4=-FLT_MAX; }
        }
    }
    __syncthreads();

    // phase 2: exact fp32 dot for each candidate
    for (int c = 0; c < 5; c++) {
        int idx = s_idx[w * 5 + c];
        const float* xr = x + ((size_t)b * 4096 + idx) * 512;
        float s = 0.f;
        #pragma unroll
        for (int k = lane; k < 512; k += 32) s = fmaf(xr[k], s_wcol[k], s);
        #pragma unroll
        for (int sh = 16; sh; sh >>= 1) s += __shfl_xor_sync(0xffffffffu, s, sh);
        if (lane == 0) s_exact[w * 5 + c] = s;
    }
    __syncthreads();

    // phase 3: exact top3 + bottom3
    if (tid == 0) {
        float mx[5], mn[5];
        #pragma unroll
        for (int i = 0; i < 5; i++) { mx[i] = s_exact[i]; mn[i] = s_exact[5 + i]; }
        float pmax = 0.f, pmin = 0.f;
        #pragma unroll
        for (int pick = 0; pick < 3; pick++) {
            int bi = 0;
            #pragma unroll
            for (int i = 1; i < 5; i++) if (mx[i] > mx[bi]) bi = i;
            pmax += mx[bi]; mx[bi] = -FLT_MAX;
            int si = 0;
            #pragma unroll
            for (int i = 1; i < 5; i++) if (mn[i] < mn[si]) si = i;
            pmin += mn[si]; mn[si] = FLT_MAX;
        }
        g_pooled[b * 128 + e] = pmax + pmin;
    }
}

// ---------------- kernel 4: L2 normalize ----------------
__global__ void normalize_kernel(float* __restrict__ out) {
    const int b = blockIdx.x, e = threadIdx.x;
    float p = g_pooled[b * 128 + e];
    __shared__ float sq[128];
    sq[e] = p * p;
    __syncthreads();
    for (int s = 64; s; s >>= 1) {
        if (e < s) sq[e] += sq[e + s];
        __syncthreads();
    }
    out[b * 128 + e] = p * rsqrtf(fmaxf(sq[0], 1e-12f));
}

// ---------------- launch ----------------
extern "C" void kernel_launch(void* const* d_in, const int* in_sizes, int n_in,
                              void* d_out, int out_size) {
    (void)in_sizes; (void)n_in; (void)out_size;
    const float* x = (const float*)d_in[0];   // [32,64,64,512] fp32
    const float* W = (const float*)d_in[1];   // [512,128] fp32
    float* out = (float*)d_out;               // [32,128] fp32

    cudaFuncSetAttribute(gemm_pool_kernel,
                         cudaFuncAttributeMaxDynamicSharedMemorySize, SM_BYTES);

    prep_B_kernel<<<256, 256>>>(W);
    gemm_pool_kernel<<<512, 512, SM_BYTES>>>(x);
    merge_pool_kernel<<<4096, 64>>>(x);
    normalize_kernel<<<32, 128>>>(out);
}

// round 14
// speedup vs baseline: 1.7067x; 1.7067x over previous
#include <cuda_runtime.h>
#include <cuda_bf16.h>
#include <cstdint>
#include <float.h>

#define DINL __device__ __forceinline__

// ---------------- scratch (__device__ globals; no allocs allowed) ----------------
__device__ __nv_bfloat16 g_B[128 * 512];        // W^T bf16, [e][k] k-contiguous
__device__ float g_WT[128 * 512];               // W^T fp32, [e][k] (for exact recompute)
__device__ float g_cand[1024 * 128 * 10];       // per-CTA per-e: 5 max (desc) + 5 min (asc)
__device__ int   g_candIdx[1024 * 128 * 10];    // row-in-batch indices for the above
__device__ float g_pooled[32 * 128];

// ---------------- helpers ----------------
DINL uint32_t smem_u32(const void* p) {
    uint32_t a;
    asm("{ .reg .u64 t; cvta.to.shared.u64 t, %1; cvt.u32.u64 %0, t; }" : "=r"(a) : "l"(p));
    return a;
}

DINL void ldmatrix4(uint32_t& r0, uint32_t& r1, uint32_t& r2, uint32_t& r3, uint32_t addr) {
    asm volatile("ldmatrix.sync.aligned.m8n8.x4.shared.b16 {%0,%1,%2,%3}, [%4];"
                 : "=r"(r0), "=r"(r1), "=r"(r2), "=r"(r3) : "r"(addr));
}

DINL void mma16816(float* c, const uint32_t* a, uint32_t b0, uint32_t b1) {
    asm volatile(
        "mma.sync.aligned.m16n8k16.row.col.f32.bf16.bf16.f32 "
        "{%0,%1,%2,%3}, {%4,%5,%6,%7}, {%8,%9}, {%0,%1,%2,%3};"
        : "+f"(c[0]), "+f"(c[1]), "+f"(c[2]), "+f"(c[3])
        : "r"(a[0]), "r"(a[1]), "r"(a[2]), "r"(a[3]), "r"(b0), "r"(b1));
}

DINL void cp_async16(uint32_t dst, const void* src) {
    asm volatile("cp.async.cg.shared.global [%0], [%1], 16;" :: "r"(dst), "l"(src) : "memory");
}
DINL void cp_commit() { asm volatile("cp.async.commit_group;" ::: "memory"); }
DINL void cp_wait1()  { asm volatile("cp.async.wait_group 1;" ::: "memory"); }

// sorted-5 insertion, max side (v0>=..>=v4)
DINL void ins5max(float v, int i, float& v0, int& i0, float& v1, int& i1,
                  float& v2, int& i2, float& v3, int& i3, float& v4, int& i4) {
    if (v > v4) {
        if (v > v2) {
            if (v > v0)      { v4=v3;i4=i3; v3=v2;i3=i2; v2=v1;i2=i1; v1=v0;i1=i0; v0=v;i0=i; }
            else if (v > v1) { v4=v3;i4=i3; v3=v2;i3=i2; v2=v1;i2=i1; v1=v;i1=i; }
            else             { v4=v3;i4=i3; v3=v2;i3=i2; v2=v;i2=i; }
        } else {
            if (v > v3)      { v4=v3;i4=i3; v3=v;i3=i; }
            else             { v4=v;i4=i; }
        }
    }
}
// sorted-5 insertion, min side (v0<=..<=v4)
DINL void ins5min(float v, int i, float& v0, int& i0, float& v1, int& i1,
                  float& v2, int& i2, float& v3, int& i3, float& v4, int& i4) {
    if (v < v4) {
        if (v < v2) {
            if (v < v0)      { v4=v3;i4=i3; v3=v2;i3=i2; v2=v1;i2=i1; v1=v0;i1=i0; v0=v;i0=i; }
            else if (v < v1) { v4=v3;i4=i3; v3=v2;i3=i2; v2=v1;i2=i1; v1=v;i1=i; }
            else             { v4=v3;i4=i3; v3=v2;i3=i2; v2=v;i2=i; }
        } else {
            if (v < v3)      { v4=v3;i4=i3; v3=v;i3=i; }
            else             { v4=v;i4=i; }
        }
    }
}

// ---------------- kernel 1: W [512,128] fp32 -> g_B bf16 + g_WT fp32 ([e][k]) ----------------
__global__ void prep_B_kernel(const float* __restrict__ W) {
    int idx = blockIdx.x * 256 + threadIdx.x;   // 65536
    int k = idx >> 7, e = idx & 127;
    float v = W[idx];
    g_B[e * 512 + k] = __float2bfloat16(v);
    g_WT[e * 512 + k] = v;
}

// ---------------- kernel 2: fully-async bf16 HMMA GEMM + per-CTA top5/bot5 ----------------
// R5 champion mainloop VERBATIM. CTA: 128 rows x 128 e, K=512 in 16 chunks of 32.
// 256 threads (8 warps, warp tile 32x64). Only the epilogue scan is parallelized 2x.
static constexpr int A32_STAGE = 16384;  // 128 rows x 32 k fp32
static constexpr int A16_STAGE = 8192;   // 128 rows x 32 k bf16
static constexpr int B_STAGE   = 8192;   // 128 e x 32 k bf16
static constexpr int OFF_A32 = 0;
static constexpr int OFF_A16 = 3 * A32_STAGE;                 // 49152
static constexpr int OFF_B   = OFF_A16 + 2 * A16_STAGE;       // 65536
static constexpr int SM_BYTES = OFF_B + 3 * B_STAGE;          // 90112 (>= 79872 epilogue)

__global__ void __launch_bounds__(256, 2) gemm_pool_kernel(const float* __restrict__ x) {
    extern __shared__ __align__(128) char smem[];
    const uint32_t sb = smem_u32(smem);
    const int tid = threadIdx.x, lane = tid & 31, wid = tid >> 5;
    const int cta = blockIdx.x;
    const float* xg = x + (size_t)cta * 128 * 512;

    // ---- cp.async staging of one K32 chunk (A: 1024x16B fp32, B: 512x16B bf16) ----
    #define ISSUE_CHUNK(kc, b3)                                                        \
    {                                                                                  \
        const uint32_t a32 = sb + OFF_A32 + (b3) * A32_STAGE;                          \
        const uint32_t bbb = sb + OFF_B + (b3) * B_STAGE;                              \
        _Pragma("unroll")                                                              \
        for (int i = 0; i < 4; i++) {                                                  \
            int u = tid + 256 * i;                                                     \
            int r = u >> 3, c = u & 7;                                                 \
            uint32_t off = (uint32_t)(r * 128 + ((c ^ (r & 7)) << 4));                 \
            cp_async16(a32 + off, xg + (size_t)r * 512 + (kc) * 32 + c * 4);           \
        }                                                                              \
        _Pragma("unroll")                                                              \
        for (int i = 0; i < 2; i++) {                                                  \
            int u = tid + 256 * i;                                                     \
            int e = u >> 2, c = u & 3;                                                 \
            uint32_t off = (uint32_t)(e * 64 + ((c ^ ((e >> 1) & 3)) << 4));           \
            cp_async16(bbb + off, (const char*)g_B + e * 1024 + (kc) * 64 + c * 16);   \
        }                                                                              \
        cp_commit();                                                                   \
    }

    // ---- convert A32[b3] -> A16[kc&1]: thread owns row r=tid>>1, half h=tid&1 ----
    #define CONVERT_A(b3, b2)                                                          \
    {                                                                                  \
        const int r = tid >> 1, h = tid & 1;                                           \
        const char* src = smem + OFF_A32 + (b3) * A32_STAGE + r * 128;                 \
        char* dst = smem + OFF_A16 + (b2) * A16_STAGE + r * 64;                        \
        uint32_t pk[8];                                                                \
        _Pragma("unroll")                                                              \
        for (int j = 0; j < 4; j++) {                                                  \
            int c = 4 * h + j;                                                         \
            float4 v = *(const float4*)(src + ((c ^ (r & 7)) << 4));                   \
            __nv_bfloat162 p01 = __floats2bfloat162_rn(v.x, v.y);                      \
            __nv_bfloat162 p23 = __floats2bfloat162_rn(v.z, v.w);                      \
            pk[j * 2] = *(uint32_t*)&p01; pk[j * 2 + 1] = *(uint32_t*)&p23;            \
        }                                                                              \
        _Pragma("unroll")                                                              \
        for (int q = 0; q < 2; q++) {                                                  \
            int c16 = 2 * h + q;                                                       \
            uint4 w4; w4.x = pk[q*4]; w4.y = pk[q*4+1]; w4.z = pk[q*4+2]; w4.w = pk[q*4+3]; \
            *(uint4*)(dst + ((c16 ^ ((r >> 1) & 3)) << 4)) = w4;                       \
        }                                                                              \
    }

    // ---- accumulators: warp tile 32(m) x 64(n), fp32 accumulate ----
    const int m0 = (wid & 3) * 32;
    const int n0 = (wid >> 2) * 64;
    float acc[16][4];
    #pragma unroll
    for (int i = 0; i < 16; i++)
        #pragma unroll
        for (int j = 0; j < 4; j++) acc[i][j] = 0.f;

    // prologue: chunks 0, 1 in flight
    ISSUE_CHUNK(0, 0);
    ISSUE_CHUNK(1, 1);

    int b3 = 0;   // kc % 3
    for (int kc = 0; kc < 16; kc++) {
        cp_wait1();          // chunk kc complete (one group may remain in flight)
        __syncthreads();     // publish chunk kc; all threads past MMA(kc-1)

        CONVERT_A(b3, kc & 1);

        int b3n = b3 + 2; if (b3n >= 3) b3n -= 3;
        if (kc + 2 < 16) { ISSUE_CHUNK(kc + 2, b3n); }
        else if (kc + 2 == 16) { cp_commit(); }   // empty group keeps wait accounting

        __syncthreads();     // A16[kc&1] fully written

        const uint32_t Ab = sb + OFF_A16 + (kc & 1) * A16_STAGE;
        const uint32_t Bb = sb + OFF_B + b3 * B_STAGE;
        #pragma unroll
        for (int ks = 0; ks < 2; ks++) {
            const int ch = ks * 2 + (lane >> 4);  // 16B chunk along k
            uint32_t a[2][4];
            #pragma unroll
            for (int mi = 0; mi < 2; mi++) {
                int r = m0 + mi * 16 + (lane & 15);
                uint32_t off = (uint32_t)(r * 64 + ((ch ^ ((r >> 1) & 3)) << 4));
                ldmatrix4(a[mi][0], a[mi][1], a[mi][2], a[mi][3], Ab + off);
            }
            uint32_t bq[4][4];
            #pragma unroll
            for (int nb = 0; nb < 4; nb++) {
                int e = n0 + nb * 16 + (lane & 15);
                uint32_t off = (uint32_t)(e * 64 + ((ch ^ ((e >> 1) & 3)) << 4));
                ldmatrix4(bq[nb][0], bq[nb][1], bq[nb][2], bq[nb][3], Bb + off);
            }
            #pragma unroll
            for (int mi = 0; mi < 2; mi++)
                #pragma unroll
                for (int ni = 0; ni < 8; ni++) {
                    int nb = ni >> 1, h = ni & 1;
                    mma16816(acc[mi * 8 + ni], a[mi], bq[nb][h], bq[nb][h + 2]);
                }
        }

        b3 = (b3 + 1 == 3) ? 0 : b3 + 1;
    }
    __syncthreads();   // all MMA reads done before smem reuse

    // ---- epilogue: acc -> smem f[128][132], then 2x-parallel per-e top5/bot5 scan ----
    float* fb = (float*)smem;
    #pragma unroll
    for (int mi = 0; mi < 2; mi++)
        #pragma unroll
        for (int ni = 0; ni < 8; ni++) {
            int r = m0 + mi * 16 + (lane >> 2);
            int c = n0 + ni * 8 + (lane & 3) * 2;
            float* a4 = acc[mi * 8 + ni];
            fb[r * 132 + c] = a4[0];
            fb[r * 132 + c + 1] = a4[1];
            fb[(r + 8) * 132 + c] = a4[2];
            fb[(r + 8) * 132 + c + 1] = a4[3];
        }
    __syncthreads();

    {
        const int e = tid & 127;
        const int h = tid >> 7;            // 0: rows 0..63, 1: rows 64..127
        float t0=-FLT_MAX,t1=-FLT_MAX,t2=-FLT_MAX,t3=-FLT_MAX,t4=-FLT_MAX;
        int   a0i=0,a1i=0,a2i=0,a3i=0,a4i=0;
        float u0=FLT_MAX,u1=FLT_MAX,u2=FLT_MAX,u3=FLT_MAX,u4=FLT_MAX;
        int   b0i=0,b1i=0,b2i=0,b3i=0,b4i=0;
        const int rbase = (cta & 31) * 128;   // row-in-batch offset
        for (int r = h * 64; r < h * 64 + 64; r++) {
            float v = fb[r * 132 + e];
            ins5max(v, rbase + r, t0,a0i, t1,a1i, t2,a2i, t3,a3i, t4,a4i);
            ins5min(v, rbase + r, u0,b0i, u1,b1i, u2,b2i, u3,b3i, u4,b4i);
        }
        __syncthreads();
        // scratch region disjoint from fb (fb ends at 67584; scratch at 69632)
        float* sc = (float*)(smem + 69632);
        if (h == 1) {
            float* p = sc + e * 20;
            p[0]=t0; p[1]=t1; p[2]=t2; p[3]=t3; p[4]=t4;
            p[5]=u0; p[6]=u1; p[7]=u2; p[8]=u3; p[9]=u4;
            int* q = (int*)(p + 10);
            q[0]=a0i; q[1]=a1i; q[2]=a2i; q[3]=a3i; q[4]=a4i;
            q[5]=b0i; q[6]=b1i; q[7]=b2i; q[8]=b3i; q[9]=b4i;
        }
        __syncthreads();
        if (h == 0) {
            const float* p = sc + e * 20;
            const int* q = (const int*)(p + 10);
            #pragma unroll
            for (int i = 0; i < 5; i++) {
                ins5max(p[i], q[i], t0,a0i, t1,a1i, t2,a2i, t3,a3i, t4,a4i);
                ins5min(p[5+i], q[5+i], u0,b0i, u1,b1i, u2,b2i, u3,b3i, u4,b4i);
            }
            size_t o = ((size_t)cta * 128 + e) * 10;
            g_cand[o+0]=t0; g_cand[o+1]=t1; g_cand[o+2]=t2; g_cand[o+3]=t3; g_cand[o+4]=t4;
            g_cand[o+5]=u0; g_cand[o+6]=u1; g_cand[o+7]=u2; g_cand[o+8]=u3; g_cand[o+9]=u4;
            g_candIdx[o+0]=a0i; g_candIdx[o+1]=a1i; g_candIdx[o+2]=a2i; g_candIdx[o+3]=a3i; g_candIdx[o+4]=a4i;
            g_candIdx[o+5]=b0i; g_candIdx[o+6]=b1i; g_candIdx[o+7]=b2i; g_candIdx[o+8]=b3i; g_candIdx[o+9]=b4i;
        }
    }
    #undef ISSUE_CHUNK
    #undef CONVERT_A
}

// ---------------- kernel 3: merge chunks, exact fp32 recompute, pool ----------------
// grid = 4096 (b*128+e), block = 64 (warp0: max side, warp1: min side)
__global__ void merge_pool_kernel(const float* __restrict__ x) {
    const int blk = blockIdx.x;
    const int b = blk >> 7, e = blk & 127;
    const int tid = threadIdx.x, lane = tid & 31, w = tid >> 5;
    __shared__ int s_idx[10];
    __shared__ float s_exact[10];
    __shared__ float s_wcol[512];

    // stage this e's fp32 W column (contiguous in g_WT) into smem
    {
        const float4* wt = (const float4*)(g_WT + (size_t)e * 512);
        ((float4*)s_wcol)[tid] = wt[tid];
        ((float4*)s_wcol)[tid + 64] = wt[tid + 64];
    }

    // phase 1: each lane owns one of 32 chunks; warp-merge its sorted-5 lists -> global top5
    {
        size_t base = (((size_t)(b * 32 + lane)) * 128 + e) * 10 + (w ? 5 : 0);
        float v0, v1, v2, v3, v4;
        int j0, j1, j2, j3, j4;
        v0 = g_cand[base+0]; v1 = g_cand[base+1]; v2 = g_cand[base+2];
        v3 = g_cand[base+3]; v4 = g_cand[base+4];
        j0 = g_candIdx[base+0]; j1 = g_candIdx[base+1]; j2 = g_candIdx[base+2];
        j3 = g_candIdx[base+3]; j4 = g_candIdx[base+4];
        if (w) { v0 = -v0; v1 = -v1; v2 = -v2; v3 = -v3; v4 = -v4; }  // min side: negate -> desc keys

        #pragma unroll
        for (int r = 0; r < 5; r++) {
            float cur = v0;
            float m = cur;
            #pragma unroll
            for (int s = 16; s; s >>= 1) m = fmaxf(m, __shfl_xor_sync(0xffffffffu, m, s));
            unsigned ball = __ballot_sync(0xffffffffu, cur == m);
            int win = __ffs(ball) - 1;
            int widx = __shfl_sync(0xffffffffu, j0, win);
            if (lane == 0) s_idx[w * 5 + r] = widx;
            if (lane == win) { v0=v1; j0=j1; v1=v2; j1=j2; v2=v3; j2=j3; v3=v4; j3=j4; v4=-FLT_MAX; }
        }
    }
    __syncthreads();

    // phase 2: exact fp32 dot for each candidate (warp handles its 5), W column from smem
    for (int c = 0; c < 5; c++) {
        int idx = s_idx[w * 5 + c];
        const float* xr = x + ((size_t)b * 4096 + idx) * 512;
        float s = 0.f;
        #pragma unroll
        for (int k = lane; k < 512; k += 32) s = fmaf(xr[k], s_wcol[k], s);
        #pragma unroll
        for (int sh = 16; sh; sh >>= 1) s += __shfl_xor_sync(0xffffffffu, s, sh);
        if (lane == 0) s_exact[w * 5 + c] = s;
    }
    __syncthreads();

    // phase 3: exact top3 + bottom3
    if (tid == 0) {
        float mx[5], mn[5];
        #pragma unroll
        for (int i = 0; i < 5; i++) { mx[i] = s_exact[i]; mn[i] = s_exact[5 + i]; }
        float pmax = 0.f, pmin = 0.f;
        #pragma unroll
        for (int pick = 0; pick < 3; pick++) {
            int bi = 0;
            #pragma unroll
            for (int i = 1; i < 5; i++) if (mx[i] > mx[bi]) bi = i;
            pmax += mx[bi]; mx[bi] = -FLT_MAX;
            int si = 0;
            #pragma unroll
            for (int i = 1; i < 5; i++) if (mn[i] < mn[si]) si = i;
            pmin += mn[si]; mn[si] = FLT_MAX;
        }
        g_pooled[b * 128 + e] = pmax + pmin;
    }
}

// ---------------- kernel 4: L2 normalize ----------------
__global__ void normalize_kernel(float* __restrict__ out) {
    const int b = blockIdx.x, e = threadIdx.x;
    float p = g_pooled[b * 128 + e];
    __shared__ float sq[128];
    sq[e] = p * p;
    __syncthreads();
    for (int s = 64; s; s >>= 1) {
        if (e < s) sq[e] += sq[e + s];
        __syncthreads();
    }
    out[b * 128 + e] = p * rsqrtf(fmaxf(sq[0], 1e-12f));
}

// ---------------- launch ----------------
extern "C" void kernel_launch(void* const* d_in, const int* in_sizes, int n_in,
                              void* d_out, int out_size) {
    (void)in_sizes; (void)n_in; (void)out_size;
    const float* x = (const float*)d_in[0];   // [32,64,64,512] fp32
    const float* W = (const float*)d_in[1];   // [512,128] fp32
    float* out = (float*)d_out;               // [32,128] fp32

    cudaFuncSetAttribute(gemm_pool_kernel,
                         cudaFuncAttributeMaxDynamicSharedMemorySize, SM_BYTES);

    prep_B_kernel<<<256, 256>>>(W);
    gemm_pool_kernel<<<1024, 256, SM_BYTES>>>(x);
    merge_pool_kernel<<<4096, 64>>>(x);
    normalize_kernel<<<32, 128>>>(out);
}